// round 2
// baseline (speedup 1.0000x reference)
#include <cuda_runtime.h>
#include <cuda_bf16.h>

#define NB_BATCH 16
#define NB_NH    32
#define NB_KVH   8
#define NB_NREP  4
#define NB_HD    128
#define NB_SCALE 0.08838834764831845f
#define NB_BPS   256      // blocks per seq
#define NB_NSPLIT 16
#define NB_CHUNK  256     // tokens per split (16 cache blocks)

// split-KV partial scratch (device globals: allocation-free)
__device__ float g_pacc[NB_BATCH * NB_KVH * NB_NSPLIT * NB_NREP * NB_HD]; // 4 MB
__device__ float g_pm[NB_BATCH * NB_KVH * NB_NSPLIT * NB_NREP];
__device__ float g_pl[NB_BATCH * NB_KVH * NB_NSPLIT * NB_NREP];

__device__ __forceinline__ void load_kv_tok(
    const float* __restrict__ kc, const float* __restrict__ vc,
    const float* __restrict__ kn, const float* __restrict__ vn,
    const int* sbt, const unsigned* ovbits, const int* sslot,
    int i, int g, int lane, float4& kk, float4& vv)
{
    const int jb = i >> 4, off = i & 15;
    const int blkid = sbt[jb];
    const size_t base = ((size_t)blkid * 16 + off) * (NB_KVH * NB_HD)
                      + (size_t)g * NB_HD + lane * 4;
    kk = *(const float4*)(kc + base);
    vv = *(const float4*)(vc + base);
    if ((ovbits[i >> 5] >> (i & 31)) & 1u) {
        // this position aliases a freshly-written slot: take new k/v instead
        const int s = blkid * 16 + off;
        int who = -1;
        #pragma unroll
        for (int bp = 0; bp < NB_BATCH; bp++)
            if (sslot[bp] == s) who = bp;   // last match wins (scatter semantics)
        if (who >= 0) {
            const size_t nb = ((size_t)who * NB_KVH + g) * NB_HD + lane * 4;
            kk = *(const float4*)(kn + nb);
            vv = *(const float4*)(vn + nb);
        }
    }
}

__global__ void attn_split(
    const float* __restrict__ q,
    const float* __restrict__ kn,
    const float* __restrict__ vn,
    const float* __restrict__ kc,
    const float* __restrict__ vc,
    const int* __restrict__ bt,
    const int* __restrict__ ctx,
    const int* __restrict__ slotmap)
{
    const int split = blockIdx.x, g = blockIdx.y, b = blockIdx.z;
    const int cl = ctx[b];
    const int j0 = split * NB_CHUNK;
    if (j0 >= cl) return;
    const int vcnt = min(NB_CHUNK, cl - j0);

    __shared__ int sbt[NB_CHUNK / 16];
    __shared__ int sslot[NB_BATCH];
    __shared__ unsigned ovbits[NB_CHUNK / 32];
    __shared__ float wm[4][NB_NREP];
    __shared__ float wl[4][NB_NREP];
    __shared__ float wacc[4][NB_NREP][NB_HD];

    const int tid = threadIdx.x;
    if (tid < 16) {
        sbt[tid]   = bt[b * NB_BPS + split * 16 + tid];
        sslot[tid] = slotmap[tid];
    }
    if (tid < NB_CHUNK / 32) ovbits[tid] = 0u;
    __syncthreads();
    if (tid == 0) {
        #pragma unroll 1
        for (int bp = 0; bp < NB_BATCH; bp++) {
            const int s = sslot[bp];
            const int sb = s >> 4, so = s & 15;
            #pragma unroll 1
            for (int jb = 0; jb < 16; jb++)
                if (sbt[jb] == sb) {
                    const int idx = jb * 16 + so;
                    ovbits[idx >> 5] |= (1u << (idx & 31));
                }
        }
    }
    __syncthreads();

    const int w = tid >> 5, lane = tid & 31;

    // Q regs: 4 GQA heads x 4 dims (lane l owns dims 4l..4l+3)
    float4 qv[NB_NREP];
    #pragma unroll
    for (int h = 0; h < NB_NREP; h++)
        qv[h] = *(const float4*)(q + ((size_t)b * NB_NH + g * NB_NREP + h) * NB_HD + lane * 4);

    float m[NB_NREP], lsum[NB_NREP];
    float4 acc[NB_NREP];
    #pragma unroll
    for (int h = 0; h < NB_NREP; h++) {
        m[h] = -1e30f; lsum[h] = 0.f;
        acc[h] = make_float4(0.f, 0.f, 0.f, 0.f);
    }

    // software-pipelined token loop: warp w takes tokens w, w+4, ...
    int i = w;
    float4 kk, vv;
    if (i < vcnt)
        load_kv_tok(kc, vc, kn, vn, sbt, ovbits, sslot, i, g, lane, kk, vv);

    while (i < vcnt) {
        const int inext = i + 4;
        float4 kk2, vv2;
        if (inext < vcnt)
            load_kv_tok(kc, vc, kn, vn, sbt, ovbits, sslot, inext, g, lane, kk2, vv2);

        float sc[NB_NREP];
        #pragma unroll
        for (int h = 0; h < NB_NREP; h++) {
            float s = qv[h].x * kk.x + qv[h].y * kk.y + qv[h].z * kk.z + qv[h].w * kk.w;
            s += __shfl_xor_sync(0xffffffffu, s, 16);
            s += __shfl_xor_sync(0xffffffffu, s, 8);
            s += __shfl_xor_sync(0xffffffffu, s, 4);
            s += __shfl_xor_sync(0xffffffffu, s, 2);
            s += __shfl_xor_sync(0xffffffffu, s, 1);
            sc[h] = s * NB_SCALE;
        }

        bool need = false;
        float mn[NB_NREP];
        #pragma unroll
        for (int h = 0; h < NB_NREP; h++) {
            mn[h] = fmaxf(m[h], sc[h]);
            need |= (mn[h] != m[h]);
        }
        if (need) {   // values are warp-replicated -> effectively uniform branch
            #pragma unroll
            for (int h = 0; h < NB_NREP; h++) {
                const float corr = __expf(m[h] - mn[h]);
                lsum[h] *= corr;
                acc[h].x *= corr; acc[h].y *= corr;
                acc[h].z *= corr; acc[h].w *= corr;
                m[h] = mn[h];
            }
        }
        #pragma unroll
        for (int h = 0; h < NB_NREP; h++) {
            const float p = __expf(sc[h] - m[h]);
            lsum[h] += p;
            acc[h].x += p * vv.x; acc[h].y += p * vv.y;
            acc[h].z += p * vv.z; acc[h].w += p * vv.w;
        }

        kk = kk2; vv = vv2; i = inext;
    }

    // per-warp -> CTA combine
    if (lane == 0) {
        #pragma unroll
        for (int h = 0; h < NB_NREP; h++) { wm[w][h] = m[h]; wl[w][h] = lsum[h]; }
    }
    #pragma unroll
    for (int h = 0; h < NB_NREP; h++)
        *(float4*)&wacc[w][h][lane * 4] = acc[h];
    __syncthreads();

    const int d = tid;  // 128 threads, one per dim
    #pragma unroll
    for (int h = 0; h < NB_NREP; h++) {
        const float M = fmaxf(fmaxf(wm[0][h], wm[1][h]), fmaxf(wm[2][h], wm[3][h]));
        const float e0 = __expf(wm[0][h] - M);
        const float e1 = __expf(wm[1][h] - M);
        const float e2 = __expf(wm[2][h] - M);
        const float e3 = __expf(wm[3][h] - M);
        const float o = wacc[0][h][d] * e0 + wacc[1][h][d] * e1
                      + wacc[2][h][d] * e2 + wacc[3][h][d] * e3;
        const size_t pidx = (((size_t)b * NB_KVH + g) * NB_NSPLIT + split) * NB_NREP + h;
        g_pacc[pidx * NB_HD + d] = o;
        if (tid == 0) {
            const float L = wl[0][h] * e0 + wl[1][h] * e1 + wl[2][h] * e2 + wl[3][h] * e3;
            g_pm[pidx] = M;
            g_pl[pidx] = L;
        }
    }
}

__global__ void attn_reduce(float* __restrict__ out, const int* __restrict__ ctx)
{
    const int bh = blockIdx.x;          // b*32 + head
    const int b = bh >> 5, hh = bh & 31;
    const int g = hh >> 2, r = hh & 3;
    const int ns = min(NB_NSPLIT, (ctx[b] + NB_CHUNK - 1) >> 8);
    const int d = threadIdx.x;

    const size_t base = ((size_t)b * NB_KVH + g) * NB_NSPLIT * NB_NREP + r;
    float M = -1e30f;
    for (int s = 0; s < ns; s++) M = fmaxf(M, g_pm[base + (size_t)s * NB_NREP]);
    float L = 0.f, o = 0.f;
    for (int s = 0; s < ns; s++) {
        const size_t pidx = base + (size_t)s * NB_NREP;
        const float e = __expf(g_pm[pidx] - M);
        L += g_pl[pidx] * e;
        o += g_pacc[pidx * NB_HD + d] * e;
    }
    out[(size_t)bh * NB_HD + d] = o * (1.f / L);
}

extern "C" void kernel_launch(void* const* d_in, const int* in_sizes, int n_in,
                              void* d_out, int out_size)
{
    const float* q    = (const float*)d_in[0];
    const float* k    = (const float*)d_in[1];
    const float* v    = (const float*)d_in[2];
    const float* kc   = (const float*)d_in[3];
    const float* vc   = (const float*)d_in[4];
    const int*   bt   = (const int*)d_in[5];
    const int*   ctx  = (const int*)d_in[6];
    const int*   slot = (const int*)d_in[7];

    dim3 grid(NB_NSPLIT, NB_KVH, NB_BATCH);
    attn_split<<<grid, 128>>>(q, k, v, kc, vc, bt, ctx, slot);
    attn_reduce<<<NB_BATCH * NB_NH, NB_HD>>>((float*)d_out, ctx);
}

// round 7
// speedup vs baseline: 1.5401x; 1.5401x over previous
#include <cuda_runtime.h>
#include <cuda_bf16.h>

#define NB_BATCH 16
#define NB_NH    32
#define NB_KVH   8
#define NB_NREP  4
#define NB_HD    128
#define NB_SCALE 0.08838834764831845f
#define NB_BPS   256
#define NB_NSPLIT 16
#define NB_CHUNK  256

// split-KV partial scratch (device globals: allocation-free)
__device__ float g_pacc[NB_BATCH * NB_KVH * NB_NSPLIT * NB_NREP * NB_HD]; // 4 MB
__device__ float g_pm[NB_BATCH * NB_KVH * NB_NSPLIT * NB_NREP];
__device__ float g_pl[NB_BATCH * NB_KVH * NB_NSPLIT * NB_NREP];

__global__ __launch_bounds__(256) void attn_split(
    const float* __restrict__ q,
    const float* __restrict__ kn,
    const float* __restrict__ vn,
    const float* __restrict__ kc,
    const float* __restrict__ vc,
    const int* __restrict__ bt,
    const int* __restrict__ ctx,
    const int* __restrict__ slotmap)
{
    const int split = blockIdx.x, g = blockIdx.y, b = blockIdx.z;
    const int cl = ctx[b];
    const int j0 = split * NB_CHUNK;
    if (j0 >= cl) return;
    const int vcnt = min(NB_CHUNK, cl - j0);

    __shared__ int   sbt[16];
    __shared__ int   sslot[16];
    __shared__ int   ovsrc[NB_CHUNK];
    __shared__ float4 sp[NB_CHUNK];          // scores, then p
    __shared__ float wred[8][4];
    __shared__ float sm[4], sl[4];
    __shared__ float wacc[8][NB_NREP][NB_HD]; // 16 KB

    const int tid = threadIdx.x;
    const int w = tid >> 5, lane = tid & 31;

    if (tid < 16) {
        sbt[tid]   = bt[b * NB_BPS + split * 16 + tid];
        sslot[tid] = slotmap[tid];
    }
    __syncthreads();
    {   // per-token override table (branchless select later)
        const int t = tid;
        const int s = sbt[t >> 4] * 16 + (t & 15);
        int ov = -1;
        #pragma unroll
        for (int bp = 0; bp < NB_BATCH; bp++)
            if (sslot[bp] == s) ov = bp;     // last match wins
        ovsrc[t] = ov;
    }
    __syncthreads();

    // ---- Pass 1: scores (K stream). 6 shfl/token, no softmax state. ----
    {
        const float* qb = q + ((size_t)b * NB_NH + g * NB_NREP) * NB_HD + lane * 4;
        const float4 q0 = *(const float4*)(qb + 0 * NB_HD);
        const float4 q1 = *(const float4*)(qb + 1 * NB_HD);
        const float4 q2 = *(const float4*)(qb + 2 * NB_HD);
        const float4 q3 = *(const float4*)(qb + 3 * NB_HD);
        const bool b0 = (lane & 1) != 0;
        const bool b1 = (lane & 2) != 0;

        #pragma unroll 4
        for (int i = 0; i < 32; i++) {
            const int t = i * 8 + w;
            if (t >= vcnt) break;            // warp-uniform
            const int ov = ovsrc[t];
            const float* kp;
            if (ov >= 0) {
                kp = kn + ((size_t)ov * NB_KVH + g) * NB_HD;
            } else {
                const int blk = sbt[t >> 4];
                kp = kc + (((size_t)blk * 16 + (t & 15)) * NB_KVH + g) * NB_HD;
            }
            const float4 kk = *(const float4*)(kp + lane * 4);

            float s0 = fmaf(q0.x, kk.x, fmaf(q0.y, kk.y, fmaf(q0.z, kk.z, q0.w * kk.w)));
            float s1 = fmaf(q1.x, kk.x, fmaf(q1.y, kk.y, fmaf(q1.z, kk.z, q1.w * kk.w)));
            float s2 = fmaf(q2.x, kk.x, fmaf(q2.y, kk.y, fmaf(q2.z, kk.z, q2.w * kk.w)));
            float s3 = fmaf(q3.x, kk.x, fmaf(q3.y, kk.y, fmaf(q3.z, kk.z, q3.w * kk.w)));

            // fold heads into lane classes: 2 + 1 + 3 shfl
            float u  = b0 ? s0 : s2;
            float vS = b0 ? s1 : s3;
            float ru = __shfl_xor_sync(0xffffffffu, u, 1);
            float rv = __shfl_xor_sync(0xffffffffu, vS, 1);
            float a0 = (b0 ? s2 : s0) + ru;   // head 2*bit0 + 0
            float a1 = (b0 ? s3 : s1) + rv;   // head 2*bit0 + 1
            float ub = b1 ? a0 : a1;
            float rb = __shfl_xor_sync(0xffffffffu, ub, 2);
            float bb = (b1 ? a1 : a0) + rb;   // head 2*bit0 + bit1
            bb += __shfl_xor_sync(0xffffffffu, bb, 4);
            bb += __shfl_xor_sync(0xffffffffu, bb, 8);
            bb += __shfl_xor_sync(0xffffffffu, bb, 16);
            if (lane < 4) {
                const int hm = ((lane & 1) << 1) | (lane >> 1);
                ((float*)&sp[t])[hm] = bb * NB_SCALE;
            }
        }
    }
    __syncthreads();

    // ---- Block softmax over the chunk (amortized) ----
    {
        const int t = tid;
        float4 s4 = sp[t];
        if (t >= vcnt) { s4.x = s4.y = s4.z = s4.w = -1e30f; }
        float m0 = s4.x, m1 = s4.y, m2 = s4.z, m3 = s4.w;
        #pragma unroll
        for (int off = 16; off >= 1; off >>= 1) {
            m0 = fmaxf(m0, __shfl_xor_sync(0xffffffffu, m0, off));
            m1 = fmaxf(m1, __shfl_xor_sync(0xffffffffu, m1, off));
            m2 = fmaxf(m2, __shfl_xor_sync(0xffffffffu, m2, off));
            m3 = fmaxf(m3, __shfl_xor_sync(0xffffffffu, m3, off));
        }
        if (lane == 0) { wred[w][0] = m0; wred[w][1] = m1; wred[w][2] = m2; wred[w][3] = m3; }
        __syncthreads();
        if (tid < 4) {
            float mm = wred[0][tid];
            #pragma unroll
            for (int ww = 1; ww < 8; ww++) mm = fmaxf(mm, wred[ww][tid]);
            sm[tid] = mm;
        }
        __syncthreads();
        const float M0 = sm[0], M1 = sm[1], M2 = sm[2], M3 = sm[3];
        float e0 = 0.f, e1 = 0.f, e2 = 0.f, e3 = 0.f;
        if (t < vcnt) {
            e0 = __expf(s4.x - M0); e1 = __expf(s4.y - M1);
            e2 = __expf(s4.z - M2); e3 = __expf(s4.w - M3);
        }
        sp[t] = make_float4(e0, e1, e2, e3);
        #pragma unroll
        for (int off = 16; off >= 1; off >>= 1) {
            e0 += __shfl_xor_sync(0xffffffffu, e0, off);
            e1 += __shfl_xor_sync(0xffffffffu, e1, off);
            e2 += __shfl_xor_sync(0xffffffffu, e2, off);
            e3 += __shfl_xor_sync(0xffffffffu, e3, off);
        }
        if (lane == 0) { wred[w][0] = e0; wred[w][1] = e1; wred[w][2] = e2; wred[w][3] = e3; }
        __syncthreads();
        if (tid < 4) {
            float ss = wred[0][tid];
            #pragma unroll
            for (int ww = 1; ww < 8; ww++) ss += wred[ww][tid];
            sl[tid] = ss;
            const size_t pidx = (((size_t)b * NB_KVH + g) * NB_NSPLIT + split) * NB_NREP + tid;
            g_pm[pidx] = sm[tid];
            g_pl[pidx] = ss;
        }
        __syncthreads();
    }

    // ---- Pass 2: output accumulation (V stream). Zero shfl, zero exp. ----
    {
        float4 a0 = make_float4(0.f,0.f,0.f,0.f), a1 = a0, a2 = a0, a3 = a0;
        #pragma unroll 4
        for (int i = 0; i < 32; i++) {
            const int t = i * 8 + w;
            if (t >= vcnt) break;
            const int ov = ovsrc[t];
            const float* vp;
            if (ov >= 0) {
                vp = vn + ((size_t)ov * NB_KVH + g) * NB_HD;
            } else {
                const int blk = sbt[t >> 4];
                vp = vc + (((size_t)blk * 16 + (t & 15)) * NB_KVH + g) * NB_HD;
            }
            const float4 vv = *(const float4*)(vp + lane * 4);
            const float4 p = sp[t];           // LDS.128 broadcast
            a0.x = fmaf(p.x, vv.x, a0.x); a0.y = fmaf(p.x, vv.y, a0.y);
            a0.z = fmaf(p.x, vv.z, a0.z); a0.w = fmaf(p.x, vv.w, a0.w);
            a1.x = fmaf(p.y, vv.x, a1.x); a1.y = fmaf(p.y, vv.y, a1.y);
            a1.z = fmaf(p.y, vv.z, a1.z); a1.w = fmaf(p.y, vv.w, a1.w);
            a2.x = fmaf(p.z, vv.x, a2.x); a2.y = fmaf(p.z, vv.y, a2.y);
            a2.z = fmaf(p.z, vv.z, a2.z); a2.w = fmaf(p.z, vv.w, a2.w);
            a3.x = fmaf(p.w, vv.x, a3.x); a3.y = fmaf(p.w, vv.y, a3.y);
            a3.z = fmaf(p.w, vv.z, a3.z); a3.w = fmaf(p.w, vv.w, a3.w);
        }
        *(float4*)&wacc[w][0][lane * 4] = a0;
        *(float4*)&wacc[w][1][lane * 4] = a1;
        *(float4*)&wacc[w][2][lane * 4] = a2;
        *(float4*)&wacc[w][3][lane * 4] = a3;
    }
    __syncthreads();

    // combine the 8 warps' partial accumulators and store (unnormalized)
    {
        const size_t pbase = (((size_t)b * NB_KVH + g) * NB_NSPLIT + split) * NB_NREP;
        #pragma unroll
        for (int o = tid; o < NB_NREP * NB_HD; o += 256) {
            const int h = o >> 7, d = o & 127;
            float s = wacc[0][h][d];
            #pragma unroll
            for (int ww = 1; ww < 8; ww++) s += wacc[ww][h][d];
            g_pacc[(pbase + h) * NB_HD + d] = s;
        }
    }
}

__global__ __launch_bounds__(128) void attn_reduce(float* __restrict__ out,
                                                   const int* __restrict__ ctx)
{
    const int bh = blockIdx.x;
    const int b = bh >> 5, hh = bh & 31;
    const int g = hh >> 2, r = hh & 3;
    const int ns = min(NB_NSPLIT, (ctx[b] + NB_CHUNK - 1) >> 8);
    const int d = threadIdx.x;

    const size_t base = ((size_t)b * NB_KVH + g) * NB_NSPLIT * NB_NREP + r;
    float M = -1e30f;
    #pragma unroll
    for (int s = 0; s < NB_NSPLIT; s++)
        if (s < ns) M = fmaxf(M, g_pm[base + (size_t)s * NB_NREP]);
    float L = 0.f, o = 0.f;
    #pragma unroll
    for (int s = 0; s < NB_NSPLIT; s++)
        if (s < ns) {
            const size_t pidx = base + (size_t)s * NB_NREP;
            const float e = __expf(g_pm[pidx] - M);
            L = fmaf(g_pl[pidx], e, L);
            o = fmaf(g_pacc[pidx * NB_HD + d], e, o);
        }
    out[(size_t)bh * NB_HD + d] = o * (1.f / L);
}

extern "C" void kernel_launch(void* const* d_in, const int* in_sizes, int n_in,
                              void* d_out, int out_size)
{
    const float* q    = (const float*)d_in[0];
    const float* k    = (const float*)d_in[1];
    const float* v    = (const float*)d_in[2];
    const float* kc   = (const float*)d_in[3];
    const float* vc   = (const float*)d_in[4];
    const int*   bt   = (const int*)d_in[5];
    const int*   ctx  = (const int*)d_in[6];
    const int*   slot = (const int*)d_in[7];

    dim3 grid(NB_NSPLIT, NB_KVH, NB_BATCH);
    attn_split<<<grid, 256>>>(q, k, v, kc, vc, bt, ctx, slot);
    attn_reduce<<<NB_BATCH * NB_NH, NB_HD>>>((float*)d_out, ctx);
}